// round 2
// baseline (speedup 1.0000x reference)
#include <cuda_runtime.h>
#include <cstdint>

#define NB 64
#define SL 510
#define NT 9
#define HID 768
#define FULLM 0xffffffffu

// Scratch (no dynamic allocation allowed)
__device__ float g_emiss[NB * SL * NT];
__device__ float g_partial[NB];

// ---------------------------------------------------------------------------
// Kernel A: emissions[b, s, t] = dot(hidden[b, s+1, :], weight[t, :]) + bias[t]
// Tile = 32 rows. K processed in 6 chunks of 128; each chunk staged into smem
// with coalesced loads (high MLP), then 288 threads (32 rows x 9 tags) read
// hidden from smem (9-way broadcast dedupe) and weight from L1 (27KB hot).
// ---------------------------------------------------------------------------
__global__ __launch_bounds__(288) void emis_kernel(
    const float* __restrict__ hidden,
    const float* __restrict__ weight,
    const float* __restrict__ bias) {
    __shared__ float hs[32][132];   // 132-float row stride: +16B bank skew

    int tid = threadIdx.x;
    int row0 = blockIdx.x * 32;
    int r = tid / NT;
    int t = tid - r * NT;
    int gr = row0 + r;

    // staging descriptors: 1024 float4 per chunk, 288 threads, up to 4 each
    const float* sp[4];
    float* dp[4];
#pragma unroll
    for (int u = 0; u < 4; u++) {
        int i = tid + u * 288;
        if (i < 1024) {
            int rr = i >> 5, jj = i & 31;
            int g2 = row0 + rr;
            int b2 = g2 / SL;
            int s2 = g2 - b2 * SL;
            sp[u] = hidden + ((size_t)(b2 * 512 + s2 + 1)) * HID + jj * 4;
            dp[u] = &hs[rr][jj * 4];
        } else {
            sp[u] = nullptr;
            dp[u] = nullptr;
        }
    }

    const float* wrow = weight + t * HID;
    float acc0 = 0.f, acc1 = 0.f;

    for (int c = 0; c < 6; c++) {
        __syncthreads();
#pragma unroll
        for (int u = 0; u < 4; u++) {
            if (sp[u]) {
                float4 v = *(const float4*)(sp[u] + c * 128);
                *(float4*)dp[u] = v;
            }
        }
        __syncthreads();

        const float4* wp = (const float4*)(wrow + c * 128);
#pragma unroll
        for (int j = 0; j < 32; j += 2) {
            float4 h0 = *(const float4*)&hs[r][j * 4];
            float4 w0 = wp[j];
            float4 h1 = *(const float4*)&hs[r][j * 4 + 4];
            float4 w1 = wp[j + 1];
            acc0 += h0.x * w0.x + h0.y * w0.y + h0.z * w0.z + h0.w * w0.w;
            acc1 += h1.x * w1.x + h1.y * w1.y + h1.z * w1.z + h1.w * w1.w;
        }
    }
    g_emiss[(size_t)gr * NT + t] = acc0 + acc1 + bias[t];
}

// ---------------------------------------------------------------------------
// Kernel B: per-batch CRF. 2 warps per block.
//   warp 0: linear-domain scaled forward (denominator) + numerator score
//   warp 1: Viterbi max-plus forward + history + parallel backtrack
// ---------------------------------------------------------------------------
__global__ __launch_bounds__(64) void crf_kernel(
    const int* __restrict__ labels,
    const float* __restrict__ start_t,
    const float* __restrict__ end_t,
    const float* __restrict__ trans,
    float* __restrict__ out) {
    __shared__ float s_trans[NT * NT];
    __shared__ unsigned char hist[(SL - 1) * 12];   // 509 rows x 12-byte pad

    int b = blockIdx.x;
    int lane = threadIdx.x & 31;
    int warp = threadIdx.x >> 5;
    bool act = lane < NT;
    int lj = act ? lane : 0;

    const float* em_base = g_emiss + (size_t)b * SL * NT;
    const int* lbl = labels + b * 512;

    if (warp == 0) {
        // ================= ALPHA (linear domain, rescaled) + NUMERATOR =====
        for (int i = lane; i < NT * NT; i += 32) s_trans[i] = trans[i];
        __syncwarp();

        float texp[NT];
#pragma unroll
        for (int i = 0; i < NT; i++) texp[i] = __expf(trans[i * NT + lj]);

        float em0 = act ? em_base[lane] : -1e30f;
        float sv = act ? (start_t[lane] + em0) : 0.f;
        float alpha = act ? __expf(sv) : 0.f;
        float acc_log = 0.f;

        int l1 = lbl[1];
        int tag0 = (l1 >= 0) ? l1 : 0;
        float score = __shfl_sync(FULLM, sv, tag0);
        int prev = tag0;

        float em_n = act ? em_base[NT + lane] : -1e30f;
        float pe_n = __expf(em_n);
        int lbl_n = lbl[2];

        for (int s = 1; s < SL; ++s) {
            float em_c = em_n;
            float pe_c = pe_n;
            int lblc = lbl_n;
            if (s + 1 < SL) {
                em_n = act ? em_base[(s + 1) * NT + lane] : -1e30f;
                lbl_n = lbl[s + 2];
            }
            pe_n = __expf(em_n);

            int m = lblc >= 0;
            int tg = m ? lblc : 0;

            float b0 = __shfl_sync(FULLM, alpha, 0);
            float b1 = __shfl_sync(FULLM, alpha, 1);
            float b2 = __shfl_sync(FULLM, alpha, 2);
            float b3 = __shfl_sync(FULLM, alpha, 3);
            float b4 = __shfl_sync(FULLM, alpha, 4);
            float b5 = __shfl_sync(FULLM, alpha, 5);
            float b6 = __shfl_sync(FULLM, alpha, 6);
            float b7 = __shfl_sync(FULLM, alpha, 7);
            float b8 = __shfl_sync(FULLM, alpha, 8);

            float d0 = b0 * texp[0] + b3 * texp[3] + b6 * texp[6];
            float d1 = b1 * texp[1] + b4 * texp[4] + b7 * texp[7];
            float d2 = b2 * texp[2] + b5 * texp[5] + b8 * texp[8];
            float an = (d0 + d1 + d2) * pe_c;
            alpha = m ? an : alpha;

            // numerator (independent chain)
            float em_tg = __shfl_sync(FULLM, em_c, tg);
            if (m) {
                score += s_trans[prev * NT + tg] + em_tg;
                prev = tg;
            }

            // rescale every 8 steps (16-lane group; lanes 9-15 hold 0)
            if ((s & 7) == 0) {
                float mx = alpha;
                mx = fmaxf(mx, __shfl_xor_sync(FULLM, mx, 8));
                mx = fmaxf(mx, __shfl_xor_sync(FULLM, mx, 4));
                mx = fmaxf(mx, __shfl_xor_sync(FULLM, mx, 2));
                mx = fmaxf(mx, __shfl_xor_sync(FULLM, mx, 1));
                alpha *= (1.0f / mx);
                acc_log += __logf(mx);
            }
        }

        float fa = act ? alpha * __expf(end_t[lane]) : 0.f;
        fa += __shfl_xor_sync(FULLM, fa, 8);
        fa += __shfl_xor_sync(FULLM, fa, 4);
        fa += __shfl_xor_sync(FULLM, fa, 2);
        fa += __shfl_xor_sync(FULLM, fa, 1);
        float den = __logf(fa) + acc_log;

        float endp = act ? end_t[lane] : 0.f;
        float numer = score + __shfl_sync(FULLM, endp, prev);

        if (lane == 0) g_partial[b] = numer - den;
    } else {
        // ================= VITERBI + HISTORY + PARALLEL BACKTRACK ==========
        float tr[NT];
#pragma unroll
        for (int i = 0; i < NT; i++) tr[i] = trans[i * NT + lj];
        float endv = act ? end_t[lane] : -1e30f;

        float vs = act ? (start_t[lane] + em_base[lane]) : -1e30f;
        float em_n = act ? em_base[NT + lane] : 0.f;
        int lbl_n = lbl[2];

        for (int s = 1; s < SL; ++s) {
            float em_c = em_n;
            int lblc = lbl_n;
            if (s + 1 < SL) {
                em_n = act ? em_base[(s + 1) * NT + lane] : 0.f;
                lbl_n = lbl[s + 2];
            }
            int m = lblc >= 0;

            float x0 = __shfl_sync(FULLM, vs, 0) + tr[0];
            float x1 = __shfl_sync(FULLM, vs, 1) + tr[1];
            float x2 = __shfl_sync(FULLM, vs, 2) + tr[2];
            float x3 = __shfl_sync(FULLM, vs, 3) + tr[3];
            float x4 = __shfl_sync(FULLM, vs, 4) + tr[4];
            float x5 = __shfl_sync(FULLM, vs, 5) + tr[5];
            float x6 = __shfl_sync(FULLM, vs, 6) + tr[6];
            float x7 = __shfl_sync(FULLM, vs, 7) + tr[7];
            float x8 = __shfl_sync(FULLM, vs, 8) + tr[8];

            // leftmost-wins max tree (matches argmax first-index tie-break)
            bool p;
            p = x1 > x0;  float v01 = p ? x1 : x0;  int i01 = p ? 1 : 0;
            p = x3 > x2;  float v23 = p ? x3 : x2;  int i23 = p ? 3 : 2;
            p = x5 > x4;  float v45 = p ? x5 : x4;  int i45 = p ? 5 : 4;
            p = x7 > x6;  float v67 = p ? x7 : x6;  int i67 = p ? 7 : 6;
            p = v23 > v01; float vA = p ? v23 : v01; int iA = p ? i23 : i01;
            p = v67 > v45; float vB = p ? v67 : v45; int iB = p ? i67 : i45;
            p = vB > vA;   float vC = p ? vB : vA;   int iC = p ? iB : iA;
            p = x8 > vC;   float vF = p ? x8 : vC;   int bi = p ? 8 : iC;

            float vn = vF + em_c;
            if (act) hist[(s - 1) * 12 + lane] = (unsigned char)(m ? bi : lane);
            if (m && act) vs = vn;
        }

        // final tag: argmax over 9 with first-index tie-break (16-lane bfly)
        float fv = vs + endv;
        int fi = act ? lane : 15;
#pragma unroll
        for (int off = 8; off > 0; off >>= 1) {
            float ov = __shfl_xor_sync(FULLM, fv, off);
            int oi = __shfl_xor_sync(FULLM, fi, off);
            bool take = (ov > fv) || (ov == fv && oi < fi);
            fv = take ? ov : fv;
            fi = take ? oi : fi;
        }
        int last = __shfl_sync(FULLM, fi, 0);
        __syncwarp();

        // ---- parallel backtrack: 16-step segment maps, nibble-packed ----
        int a = lane * 16;
        int bnd = a + 16 < (SL - 1) ? a + 16 : (SL - 1);   // clamp to 509
        unsigned long long F = 0x876543210ull;             // identity map
        for (int s = bnd - 1; s >= a; --s) {
            const unsigned char* hr = hist + s * 12;
            unsigned long long nF = 0;
#pragma unroll
            for (int t = 0; t < NT; t++) {
                int e = (int)((F >> (4 * t)) & 15);
                nF |= ((unsigned long long)hr[e]) << (4 * t);
            }
            F = nF;
        }

        // serial combine over 31 lane-maps (descending)
        unsigned int flo = (unsigned int)F;
        unsigned int fhi = (unsigned int)(F >> 32);
        int cur = last;          // state at position 509
        int my_entry = (lane == 31) ? last : 0;
        for (int l = 31; l >= 1; --l) {
            unsigned int lo = __shfl_sync(FULLM, flo, l);
            unsigned int hi = __shfl_sync(FULLM, fhi, l);
            unsigned long long Fl = ((unsigned long long)hi << 32) | lo;
            cur = (int)((Fl >> (4 * cur)) & 15);   // state at pos l*16
            if (lane == l - 1) my_entry = cur;
        }

        // replay + write tags
        float* otag = out + 1 + (size_t)b * SL;
        if (lane == 31) {
            otag[SL - 1] = (lbl[SL] >= 0) ? (float)last : 0.f;
        }
        int c2 = my_entry;       // state at position bnd
        for (int s = bnd - 1; s >= a; --s) {
            c2 = hist[s * 12 + c2];
            otag[s] = (lbl[s + 1] >= 0) ? (float)c2 : 0.f;
        }
    }
}

// ---------------------------------------------------------------------------
// Kernel C: out[0] = -sum_b partial[b]
// ---------------------------------------------------------------------------
__global__ __launch_bounds__(32) void reduce_kernel(float* __restrict__ out) {
    int l = threadIdx.x;
    float v = g_partial[l] + g_partial[l + 32];
#pragma unroll
    for (int o = 16; o > 0; o >>= 1) v += __shfl_xor_sync(FULLM, v, o);
    if (l == 0) out[0] = -v;
}

// ---------------------------------------------------------------------------
extern "C" void kernel_launch(void* const* d_in, const int* in_sizes, int n_in,
                              void* d_out, int out_size) {
    const float* hidden  = (const float*)d_in[0];
    const int*   labels  = (const int*)d_in[1];
    const float* weight  = (const float*)d_in[2];
    const float* bias    = (const float*)d_in[3];
    const float* start_t = (const float*)d_in[4];
    const float* end_t   = (const float*)d_in[5];
    const float* trans   = (const float*)d_in[6];
    float* out = (float*)d_out;

    emis_kernel<<<(NB * SL) / 32, 288>>>(hidden, weight, bias);
    crf_kernel<<<NB, 64>>>(labels, start_t, end_t, trans, out);
    reduce_kernel<<<1, 32>>>(out);
}

// round 3
// speedup vs baseline: 2.2221x; 2.2221x over previous
#include <cuda_runtime.h>
#include <cstdint>

#define NB 64
#define SL 510
#define SLP 526          // padded step stride (prefetch overrun room)
#define NT 9
#define HID 768
#define FULLM 0xffffffffu

// Scratch (no dynamic allocation allowed)
__device__ float g_emiss[NB * SLP * NT];   // zero-init; pad rows stay 0 (masked)
__device__ float g_partial[NB];

// ---------------------------------------------------------------------------
// Kernel A: emissions[b, s, t] = dot(hidden[b, s+1, :], weight[t, :]) + bias[t]
// Warp-per-row-pair: warp cooperatively loads 2 hidden rows (coalesced
// LDG.128), weight from smem (lane-stride 16B -> conflict-free LDS.128,
// reused for both rows), 9 accumulators per row reduced via bfly shfl.
// ---------------------------------------------------------------------------
__global__ __launch_bounds__(128) void emis_kernel(
    const float* __restrict__ hidden,
    const float* __restrict__ weight,
    const float* __restrict__ bias) {
    __shared__ float ws[NT * HID];
    __shared__ float bs[NT];

    int tid = threadIdx.x;
    for (int i = tid; i < NT * HID / 4; i += 128)
        ((float4*)ws)[i] = ((const float4*)weight)[i];
    if (tid < NT) bs[tid] = bias[tid];
    __syncthreads();

    int lane = tid & 31;
    int gw = blockIdx.x * 4 + (tid >> 5);   // 1020 warps, 32 rows each
    int r0 = gw * 32;
    int b = r0 / SL;
    int s = r0 - b * SL;

    for (int p = 0; p < 16; ++p) {          // 16 passes x 2 rows
        // row 0 of pair
        int b0 = b, s0 = s;
        if (++s == SL) { s = 0; ++b; }
        int b1 = b, s1 = s;
        if (++s == SL) { s = 0; ++b; }

        const float4* hp0 = (const float4*)(hidden + (size_t)(b0 * 512 + s0 + 1) * HID);
        const float4* hp1 = (const float4*)(hidden + (size_t)(b1 * 512 + s1 + 1) * HID);

        float4 h0[6], h1[6];
#pragma unroll
        for (int u = 0; u < 6; u++) h0[u] = hp0[u * 32 + lane];
#pragma unroll
        for (int u = 0; u < 6; u++) h1[u] = hp1[u * 32 + lane];

        float a0[NT], a1[NT];
#pragma unroll
        for (int t = 0; t < NT; t++) { a0[t] = 0.f; a1[t] = 0.f; }

#pragma unroll
        for (int u = 0; u < 6; u++) {
#pragma unroll
            for (int t = 0; t < NT; t++) {
                float4 w = ((const float4*)(ws + t * HID))[u * 32 + lane];
                a0[t] += h0[u].x * w.x + h0[u].y * w.y + h0[u].z * w.z + h0[u].w * w.w;
                a1[t] += h1[u].x * w.x + h1[u].y * w.y + h1[u].z * w.z + h1[u].w * w.w;
            }
        }

#pragma unroll
        for (int t = 0; t < NT; t++) {
#pragma unroll
            for (int off = 16; off > 0; off >>= 1) {
                a0[t] += __shfl_xor_sync(FULLM, a0[t], off);
                a1[t] += __shfl_xor_sync(FULLM, a1[t], off);
            }
        }

        if (lane == 0) {
            float* o0 = g_emiss + ((size_t)b0 * SLP + s0) * NT;
            float* o1 = g_emiss + ((size_t)b1 * SLP + s1) * NT;
#pragma unroll
            for (int t = 0; t < NT; t++) o0[t] = a0[t] + bs[t];
#pragma unroll
            for (int t = 0; t < NT; t++) o1[t] = a1[t] + bs[t];
        }
    }
}

// ---------------------------------------------------------------------------
// Kernel B: per-batch CRF, 1 warp per block, 2 blocks per batch:
//   role 0: linear-domain scaled forward (denominator) + numerator score
//   role 1: Viterbi max-plus forward + history + parallel backtrack
// Emissions prefetched via 8-deep register ring (hides L2 latency);
// labels staged in smem.
// ---------------------------------------------------------------------------
__global__ __launch_bounds__(32) void crf_kernel(
    const int* __restrict__ labels,
    const float* __restrict__ start_t,
    const float* __restrict__ end_t,
    const float* __restrict__ trans,
    float* __restrict__ out) {
    __shared__ int s_lbl[528];
    __shared__ float s_trans[NT * NT];
    __shared__ unsigned char hist[(SL - 1) * 12];

    int blk = blockIdx.x;
    int b = blk >> 1;
    int role = blk & 1;
    int lane = threadIdx.x;
    bool act = lane < NT;
    int lj = act ? lane : 0;

    const float* em_base = g_emiss + (size_t)b * SLP * NT;
    const int* lbl = labels + b * 512;

    // stage labels; pad mask region (indices 511..527) with -1
    for (int i = lane; i < 512; i += 32) s_lbl[i] = lbl[i];
    __syncwarp();
    if (lane < 17) s_lbl[511 + lane] = -1;
    __syncwarp();

    if (role == 0) {
        // ================= ALPHA (linear domain, rescaled) + NUMERATOR =====
        for (int i = lane; i < NT * NT; i += 32) s_trans[i] = trans[i];

        float texp[NT];
#pragma unroll
        for (int i = 0; i < NT; i++) texp[i] = __expf(trans[i * NT + lj]);
        __syncwarp();

        float em0 = act ? em_base[lane] : -1e30f;
        float sv = act ? (start_t[lane] + em0) : 0.f;
        float alpha = act ? __expf(sv) : 0.f;
        float acc_log = 0.f;

        int l1 = s_lbl[1];
        int tag0 = (l1 >= 0) ? l1 : 0;
        float score = __shfl_sync(FULLM, sv, tag0);
        int prev = tag0;

        float em_ring[8], pe_ring[8];
#pragma unroll
        for (int u = 0; u < 8; u++) {
            em_ring[u] = act ? em_base[(1 + u) * NT + lane] : -1e30f;
            pe_ring[u] = __expf(em_ring[u]);
        }

        for (int s0 = 1; s0 < 513; s0 += 8) {
#pragma unroll
            for (int u = 0; u < 8; u++) {
                int s = s0 + u;
                float em_c = em_ring[u];
                float pe_c = pe_ring[u];
                // refill ring 8 steps ahead
                em_ring[u] = act ? em_base[(s + 8) * NT + lane] : -1e30f;
                pe_ring[u] = __expf(em_ring[u]);

                int lblc = s_lbl[s + 1];
                int m = lblc >= 0;
                int tg = m ? lblc : 0;

                float b0 = __shfl_sync(FULLM, alpha, 0);
                float b1 = __shfl_sync(FULLM, alpha, 1);
                float b2 = __shfl_sync(FULLM, alpha, 2);
                float b3 = __shfl_sync(FULLM, alpha, 3);
                float b4 = __shfl_sync(FULLM, alpha, 4);
                float b5 = __shfl_sync(FULLM, alpha, 5);
                float b6 = __shfl_sync(FULLM, alpha, 6);
                float b7 = __shfl_sync(FULLM, alpha, 7);
                float b8 = __shfl_sync(FULLM, alpha, 8);

                float d0 = b0 * texp[0] + b3 * texp[3] + b6 * texp[6];
                float d1 = b1 * texp[1] + b4 * texp[4] + b7 * texp[7];
                float d2 = b2 * texp[2] + b5 * texp[5] + b8 * texp[8];
                float an = (d0 + d1 + d2) * pe_c;
                alpha = m ? an : alpha;

                // numerator chain (independent)
                float em_tg = __shfl_sync(FULLM, em_c, tg);
                if (m) {
                    score += s_trans[prev * NT + tg] + em_tg;
                    prev = tg;
                }

                if ((s & 7) == 0) {
                    float mx = alpha;
                    mx = fmaxf(mx, __shfl_xor_sync(FULLM, mx, 8));
                    mx = fmaxf(mx, __shfl_xor_sync(FULLM, mx, 4));
                    mx = fmaxf(mx, __shfl_xor_sync(FULLM, mx, 2));
                    mx = fmaxf(mx, __shfl_xor_sync(FULLM, mx, 1));
                    alpha *= (1.0f / mx);
                    acc_log += __logf(mx);
                }
            }
        }

        float fa = act ? alpha * __expf(end_t[lane]) : 0.f;
        fa += __shfl_xor_sync(FULLM, fa, 8);
        fa += __shfl_xor_sync(FULLM, fa, 4);
        fa += __shfl_xor_sync(FULLM, fa, 2);
        fa += __shfl_xor_sync(FULLM, fa, 1);
        float den = __logf(fa) + acc_log;

        float endp = act ? end_t[lane] : 0.f;
        float numer = score + __shfl_sync(FULLM, endp, prev);

        if (lane == 0) g_partial[b] = numer - den;
    } else {
        // ================= VITERBI + HISTORY + PARALLEL BACKTRACK ==========
        float tr[NT];
#pragma unroll
        for (int i = 0; i < NT; i++) tr[i] = trans[i * NT + lj];
        float endv = act ? end_t[lane] : -1e30f;

        float vs = act ? (start_t[lane] + em_base[lane]) : -1e30f;

        float em_ring[8];
#pragma unroll
        for (int u = 0; u < 8; u++)
            em_ring[u] = act ? em_base[(1 + u) * NT + lane] : 0.f;

        for (int s0 = 1; s0 < 513; s0 += 8) {
#pragma unroll
            for (int u = 0; u < 8; u++) {
                int s = s0 + u;
                float em_c = em_ring[u];
                em_ring[u] = act ? em_base[(s + 8) * NT + lane] : 0.f;

                int lblc = s_lbl[s + 1];
                int m = lblc >= 0;

                float x0 = __shfl_sync(FULLM, vs, 0) + tr[0];
                float x1 = __shfl_sync(FULLM, vs, 1) + tr[1];
                float x2 = __shfl_sync(FULLM, vs, 2) + tr[2];
                float x3 = __shfl_sync(FULLM, vs, 3) + tr[3];
                float x4 = __shfl_sync(FULLM, vs, 4) + tr[4];
                float x5 = __shfl_sync(FULLM, vs, 5) + tr[5];
                float x6 = __shfl_sync(FULLM, vs, 6) + tr[6];
                float x7 = __shfl_sync(FULLM, vs, 7) + tr[7];
                float x8 = __shfl_sync(FULLM, vs, 8) + tr[8];

                // value via fmax tree (critical path); argmax off-path below
                float mA = fmaxf(fmaxf(fmaxf(x0, x1), fmaxf(x2, x3)),
                                 fmaxf(fmaxf(x4, x5), fmaxf(x6, fmaxf(x7, x8))));
                float vn = mA + em_c;
                if (m && act) vs = vn;

                // first-index argmax (descending predicated writes)
                int bi = 8;
                if (x7 == mA) bi = 7;
                if (x6 == mA) bi = 6;
                if (x5 == mA) bi = 5;
                if (x4 == mA) bi = 4;
                if (x3 == mA) bi = 3;
                if (x2 == mA) bi = 2;
                if (x1 == mA) bi = 1;
                if (x0 == mA) bi = 0;

                if (act && s < SL)
                    hist[(s - 1) * 12 + lane] = (unsigned char)(m ? bi : lane);
            }
        }

        // final tag: argmax over 9 with first-index tie-break (16-lane bfly)
        float fv = vs + endv;
        int fi = act ? lane : 15;
#pragma unroll
        for (int off = 8; off > 0; off >>= 1) {
            float ov = __shfl_xor_sync(FULLM, fv, off);
            int oi = __shfl_xor_sync(FULLM, fi, off);
            bool take = (ov > fv) || (ov == fv && oi < fi);
            fv = take ? ov : fv;
            fi = take ? oi : fi;
        }
        int last = __shfl_sync(FULLM, fi, 0);
        __syncwarp();

        // ---- parallel backtrack: 16-step segment maps, nibble-packed ----
        int a = lane * 16;
        int bnd = a + 16 < (SL - 1) ? a + 16 : (SL - 1);   // clamp to 509
        unsigned long long F = 0x876543210ull;             // identity map
        for (int s = bnd - 1; s >= a; --s) {
            const unsigned char* hr = hist + s * 12;
            unsigned long long nF = 0;
#pragma unroll
            for (int t = 0; t < NT; t++) {
                int e = (int)((F >> (4 * t)) & 15);
                nF |= ((unsigned long long)hr[e]) << (4 * t);
            }
            F = nF;
        }

        unsigned int flo = (unsigned int)F;
        unsigned int fhi = (unsigned int)(F >> 32);
        int cur = last;          // state at position 509
        int my_entry = (lane == 31) ? last : 0;
        for (int l = 31; l >= 1; --l) {
            unsigned int lo = __shfl_sync(FULLM, flo, l);
            unsigned int hi = __shfl_sync(FULLM, fhi, l);
            unsigned long long Fl = ((unsigned long long)hi << 32) | lo;
            cur = (int)((Fl >> (4 * cur)) & 15);   // state at pos l*16
            if (lane == l - 1) my_entry = cur;
        }

        float* otag = out + 1 + (size_t)b * SL;
        if (lane == 31) {
            otag[SL - 1] = (s_lbl[SL] >= 0) ? (float)last : 0.f;
        }
        int c2 = my_entry;       // state at position bnd
        for (int s = bnd - 1; s >= a; --s) {
            c2 = hist[s * 12 + c2];
            otag[s] = (s_lbl[s + 1] >= 0) ? (float)c2 : 0.f;
        }
    }
}

// ---------------------------------------------------------------------------
// Kernel C: out[0] = -sum_b partial[b]
// ---------------------------------------------------------------------------
__global__ __launch_bounds__(32) void reduce_kernel(float* __restrict__ out) {
    int l = threadIdx.x;
    float v = g_partial[l] + g_partial[l + 32];
#pragma unroll
    for (int o = 16; o > 0; o >>= 1) v += __shfl_xor_sync(FULLM, v, o);
    if (l == 0) out[0] = -v;
}

// ---------------------------------------------------------------------------
extern "C" void kernel_launch(void* const* d_in, const int* in_sizes, int n_in,
                              void* d_out, int out_size) {
    const float* hidden  = (const float*)d_in[0];
    const int*   labels  = (const int*)d_in[1];
    const float* weight  = (const float*)d_in[2];
    const float* bias    = (const float*)d_in[3];
    const float* start_t = (const float*)d_in[4];
    const float* end_t   = (const float*)d_in[5];
    const float* trans   = (const float*)d_in[6];
    float* out = (float*)d_out;

    emis_kernel<<<255, 128>>>(hidden, weight, bias);
    crf_kernel<<<2 * NB, 32>>>(labels, start_t, end_t, trans, out);
    reduce_kernel<<<1, 32>>>(out);
}

// round 4
// speedup vs baseline: 3.1752x; 1.4289x over previous
#include <cuda_runtime.h>
#include <cstdint>

#define NB 64
#define SL 510
#define SLP 532          // padded step stride (prefetch overrun room, >= 529)
#define NT 9
#define HID 768
#define FULLM 0xffffffffu

// Scratch (no dynamic allocation allowed). Zero-initialized at load; pad rows
// (s >= 510) are never written -> stay 0 forever (masked in CRF).
__device__ float g_emiss[NB * SLP * NT];
__device__ float g_partial[NB];

// ---------------------------------------------------------------------------
// Kernel A: emissions[b, s, t] = dot(hidden[b, s+1, :], weight[t, :]) + bias[t]
// Thread-per-row. Hidden staged via smem in 24 chunks of 32 floats/row:
// warp-coalesced LDG (4x128B lines/instr), STS, then each thread reads its own
// row from smem at float4 stride 9 (conflict-free), weight via smem broadcast.
// Register double-buffering overlaps next chunk's LDG with current compute.
// ---------------------------------------------------------------------------
__global__ __launch_bounds__(128) void emis_kernel(
    const float* __restrict__ hidden,
    const float* __restrict__ weight,
    const float* __restrict__ bias) {
    __shared__ float4 ws4[NT * 192];        // 27,648 B
    __shared__ float4 hs4[128 * 9];         // 18,432 B (row stride 9 float4)
    __shared__ float bs[NT];

    int tid = threadIdx.x;

    // stage weight + bias
    for (int i = tid; i < NT * 192; i += 128)
        ws4[i] = ((const float4*)weight)[i];
    if (tid < NT) bs[tid] = bias[tid];

    // per-thread staging descriptors: 8 (row, j) slots per chunk
    const float4* src[8];
    int dsti[8];
#pragma unroll
    for (int u = 0; u < 8; u++) {
        int idx = u * 128 + tid;
        int row = idx >> 3, j = idx & 7;
        int gr = blockIdx.x * 128 + row;
        int b2 = gr / SL, s2 = gr - b2 * SL;
        src[u] = (const float4*)(hidden + (size_t)(b2 * 512 + s2 + 1) * HID) + j;
        dsti[u] = row * 9 + j;
    }

    // own row
    int gr = blockIdx.x * 128 + tid;
    int b = gr / SL, s = gr - b * SL;

    float acc[NT];
#pragma unroll
    for (int t = 0; t < NT; t++) acc[t] = 0.f;

    // prologue: chunk 0 into registers
    float4 pre[8];
#pragma unroll
    for (int u = 0; u < 8; u++) pre[u] = src[u][0];

    for (int c = 0; c < 24; c++) {
        __syncthreads();                    // prev compute done reading hs4
#pragma unroll
        for (int u = 0; u < 8; u++) hs4[dsti[u]] = pre[u];
        __syncthreads();

        if (c + 1 < 24) {
#pragma unroll
            for (int u = 0; u < 8; u++) pre[u] = src[u][(c + 1) * 8];
        }

        const float4* hb = hs4 + tid * 9;
#pragma unroll
        for (int j = 0; j < 8; j++) {
            float4 h = hb[j];
#pragma unroll
            for (int t = 0; t < NT; t++) {
                float4 w = ws4[t * 192 + c * 8 + j];
                acc[t] = fmaf(h.x, w.x, fmaf(h.y, w.y,
                         fmaf(h.z, w.z, fmaf(h.w, w.w, acc[t]))));
            }
        }
    }

    float* o = g_emiss + ((size_t)b * SLP + s) * NT;
#pragma unroll
    for (int t = 0; t < NT; t++) o[t] = acc[t] + bs[t];
}

// ---------------------------------------------------------------------------
// Kernel B: per-batch CRF, 1 warp per block, 2 blocks per batch:
//   role 0: linear-domain scaled forward (denominator) + numerator score
//           (depth-16 emission pipeline: LDG 16 ahead, exp 8 ahead)
//   role 1: Viterbi max-plus forward + history + parallel backtrack
// ---------------------------------------------------------------------------
__global__ __launch_bounds__(32) void crf_kernel(
    const int* __restrict__ labels,
    const float* __restrict__ start_t,
    const float* __restrict__ end_t,
    const float* __restrict__ trans,
    float* __restrict__ out) {
    __shared__ int s_lbl[528];
    __shared__ float s_trans[NT * NT];
    __shared__ unsigned char hist[(SL - 1) * 12];

    int blk = blockIdx.x;
    int b = blk >> 1;
    int role = blk & 1;
    int lane = threadIdx.x;
    bool act = lane < NT;
    int lj = act ? lane : 0;

    const float* em_base = g_emiss + (size_t)b * SLP * NT;
    const int* lbl = labels + b * 512;

    // stage labels; pad mask region (indices 511..527) with -1
    for (int i = lane; i < 512; i += 32) s_lbl[i] = lbl[i];
    __syncwarp();
    if (lane < 17) s_lbl[511 + lane] = -1;
    __syncwarp();

    if (role == 0) {
        // ============== ALPHA (linear, power-2 rescaled) + NUMERATOR =======
        for (int i = lane; i < NT * NT; i += 32) s_trans[i] = trans[i];

        float texp[NT];
#pragma unroll
        for (int i = 0; i < NT; i++) texp[i] = __expf(trans[i * NT + lj]);
        __syncwarp();

        float em0 = act ? em_base[lane] : -1e30f;
        float sv = act ? (start_t[lane] + em0) : 0.f;
        float alpha = act ? __expf(sv) : 0.f;
        int acc_e = 0;

        int l1 = s_lbl[1];
        int tag0 = (l1 >= 0) ? l1 : 0;
        float score = __shfl_sync(FULLM, sv, tag0);
        int prev = tag0;

        // depth-16 pipeline: em_nxt = raw loads (16 ahead);
        // em_cur/pe_cur = value+exp ready for consumption (exp computed
        // 8 steps after its load -> no load-use stall).
        float em_cur[8], pe_cur[8], em_nxt[8];
#pragma unroll
        for (int u = 0; u < 8; u++)
            em_cur[u] = act ? em_base[(1 + u) * NT + lane] : -1e30f;
#pragma unroll
        for (int u = 0; u < 8; u++) pe_cur[u] = __expf(em_cur[u]);
#pragma unroll
        for (int u = 0; u < 8; u++)
            em_nxt[u] = act ? em_base[(9 + u) * NT + lane] : -1e30f;

        for (int s0 = 1; s0 < 513; s0 += 8) {
#pragma unroll
            for (int u = 0; u < 8; u++) {
                int s = s0 + u;
                float em_c = em_cur[u];
                float pe_c = pe_cur[u];
                // promote: exp of value loaded 8 steps ago (no stall)
                em_cur[u] = em_nxt[u];
                pe_cur[u] = __expf(em_nxt[u]);
                // issue load 16 steps ahead (max index 528 < SLP)
                em_nxt[u] = act ? em_base[(s + 16) * NT + lane] : -1e30f;

                int lblc = s_lbl[s + 1];
                int m = lblc >= 0;
                int tg = m ? lblc : 0;

                float b0 = __shfl_sync(FULLM, alpha, 0);
                float b1 = __shfl_sync(FULLM, alpha, 1);
                float b2 = __shfl_sync(FULLM, alpha, 2);
                float b3 = __shfl_sync(FULLM, alpha, 3);
                float b4 = __shfl_sync(FULLM, alpha, 4);
                float b5 = __shfl_sync(FULLM, alpha, 5);
                float b6 = __shfl_sync(FULLM, alpha, 6);
                float b7 = __shfl_sync(FULLM, alpha, 7);
                float b8 = __shfl_sync(FULLM, alpha, 8);

                float d0 = b0 * texp[0] + b3 * texp[3] + b6 * texp[6];
                float d1 = b1 * texp[1] + b4 * texp[4] + b7 * texp[7];
                float d2 = b2 * texp[2] + b5 * texp[5] + b8 * texp[8];
                float an = (d0 + d1 + d2) * pe_c;
                alpha = m ? an : alpha;

                // numerator chain (independent)
                float em_tg = __shfl_sync(FULLM, em_c, tg);
                if (m) {
                    score += s_trans[prev * NT + tg] + em_tg;
                    prev = tg;
                }

                // power-of-2 rescale every 8 steps (exact, 1 shfl + ALU)
                if ((s & 7) == 0) {
                    float ref = __shfl_sync(FULLM, alpha, 4);
                    int Eb = (__float_as_int(ref) >> 23) & 0xff;
                    int Es = Eb ? Eb : 127;
                    float scale = __int_as_float((254 - Es) << 23);
                    alpha *= scale;
                    acc_e += Es - 127;
                }
            }
        }

        float fa = act ? alpha * __expf(end_t[lane]) : 0.f;
        fa += __shfl_xor_sync(FULLM, fa, 8);
        fa += __shfl_xor_sync(FULLM, fa, 4);
        fa += __shfl_xor_sync(FULLM, fa, 2);
        fa += __shfl_xor_sync(FULLM, fa, 1);
        float den = __logf(fa) + (float)acc_e * 0.69314718056f;

        float endp = act ? end_t[lane] : 0.f;
        float numer = score + __shfl_sync(FULLM, endp, prev);

        if (lane == 0) g_partial[b] = numer - den;
    } else {
        // ================= VITERBI + HISTORY + PARALLEL BACKTRACK ==========
        float tr[NT];
#pragma unroll
        for (int i = 0; i < NT; i++) tr[i] = trans[i * NT + lj];
        float endv = act ? end_t[lane] : -1e30f;

        float vs = act ? (start_t[lane] + em_base[lane]) : -1e30f;

        float em_ring[8];
#pragma unroll
        for (int u = 0; u < 8; u++)
            em_ring[u] = act ? em_base[(1 + u) * NT + lane] : 0.f;

        for (int s0 = 1; s0 < 513; s0 += 8) {
#pragma unroll
            for (int u = 0; u < 8; u++) {
                int s = s0 + u;
                float em_c = em_ring[u];
                em_ring[u] = act ? em_base[(s + 8) * NT + lane] : 0.f;

                int lblc = s_lbl[s + 1];
                int m = lblc >= 0;

                float x0 = __shfl_sync(FULLM, vs, 0) + tr[0];
                float x1 = __shfl_sync(FULLM, vs, 1) + tr[1];
                float x2 = __shfl_sync(FULLM, vs, 2) + tr[2];
                float x3 = __shfl_sync(FULLM, vs, 3) + tr[3];
                float x4 = __shfl_sync(FULLM, vs, 4) + tr[4];
                float x5 = __shfl_sync(FULLM, vs, 5) + tr[5];
                float x6 = __shfl_sync(FULLM, vs, 6) + tr[6];
                float x7 = __shfl_sync(FULLM, vs, 7) + tr[7];
                float x8 = __shfl_sync(FULLM, vs, 8) + tr[8];

                // value via fmax tree (critical path); argmax off-path below
                float mA = fmaxf(fmaxf(fmaxf(x0, x1), fmaxf(x2, x3)),
                                 fmaxf(fmaxf(x4, x5), fmaxf(x6, fmaxf(x7, x8))));
                float vn = mA + em_c;
                if (m && act) vs = vn;

                // first-index argmax (descending predicated writes)
                int bi = 8;
                if (x7 == mA) bi = 7;
                if (x6 == mA) bi = 6;
                if (x5 == mA) bi = 5;
                if (x4 == mA) bi = 4;
                if (x3 == mA) bi = 3;
                if (x2 == mA) bi = 2;
                if (x1 == mA) bi = 1;
                if (x0 == mA) bi = 0;

                if (act && s < SL)
                    hist[(s - 1) * 12 + lane] = (unsigned char)(m ? bi : lane);
            }
        }

        // final tag: argmax over 9 with first-index tie-break (16-lane bfly)
        float fv = vs + endv;
        int fi = act ? lane : 15;
#pragma unroll
        for (int off = 8; off > 0; off >>= 1) {
            float ov = __shfl_xor_sync(FULLM, fv, off);
            int oi = __shfl_xor_sync(FULLM, fi, off);
            bool take = (ov > fv) || (ov == fv && oi < fi);
            fv = take ? ov : fv;
            fi = take ? oi : fi;
        }
        int last = __shfl_sync(FULLM, fi, 0);
        __syncwarp();

        // ---- parallel backtrack: 16-step segment maps, nibble-packed ----
        int a = lane * 16;
        int bnd = a + 16 < (SL - 1) ? a + 16 : (SL - 1);   // clamp to 509
        unsigned long long F = 0x876543210ull;             // identity map
        for (int s = bnd - 1; s >= a; --s) {
            const unsigned char* hr = hist + s * 12;
            unsigned long long nF = 0;
#pragma unroll
            for (int t = 0; t < NT; t++) {
                int e = (int)((F >> (4 * t)) & 15);
                nF |= ((unsigned long long)hr[e]) << (4 * t);
            }
            F = nF;
        }

        unsigned int flo = (unsigned int)F;
        unsigned int fhi = (unsigned int)(F >> 32);
        int cur = last;          // state at position 509
        int my_entry = (lane == 31) ? last : 0;
        for (int l = 31; l >= 1; --l) {
            unsigned int lo = __shfl_sync(FULLM, flo, l);
            unsigned int hi = __shfl_sync(FULLM, fhi, l);
            unsigned long long Fl = ((unsigned long long)hi << 32) | lo;
            cur = (int)((Fl >> (4 * cur)) & 15);   // state at pos l*16
            if (lane == l - 1) my_entry = cur;
        }

        float* otag = out + 1 + (size_t)b * SL;
        if (lane == 31) {
            otag[SL - 1] = (s_lbl[SL] >= 0) ? (float)last : 0.f;
        }
        int c2 = my_entry;       // state at position bnd
        for (int s = bnd - 1; s >= a; --s) {
            c2 = hist[s * 12 + c2];
            otag[s] = (s_lbl[s + 1] >= 0) ? (float)c2 : 0.f;
        }
    }
}

// ---------------------------------------------------------------------------
// Kernel C: out[0] = -sum_b partial[b]
// ---------------------------------------------------------------------------
__global__ __launch_bounds__(32) void reduce_kernel(float* __restrict__ out) {
    int l = threadIdx.x;
    float v = g_partial[l] + g_partial[l + 32];
#pragma unroll
    for (int o = 16; o > 0; o >>= 1) v += __shfl_xor_sync(FULLM, v, o);
    if (l == 0) out[0] = -v;
}

// ---------------------------------------------------------------------------
extern "C" void kernel_launch(void* const* d_in, const int* in_sizes, int n_in,
                              void* d_out, int out_size) {
    const float* hidden  = (const float*)d_in[0];
    const int*   labels  = (const int*)d_in[1];
    const float* weight  = (const float*)d_in[2];
    const float* bias    = (const float*)d_in[3];
    const float* start_t = (const float*)d_in[4];
    const float* end_t   = (const float*)d_in[5];
    const float* trans   = (const float*)d_in[6];
    float* out = (float*)d_out;

    emis_kernel<<<255, 128>>>(hidden, weight, bias);
    crf_kernel<<<2 * NB, 32>>>(labels, start_t, end_t, trans, out);
    reduce_kernel<<<1, 32>>>(out);
}

// round 5
// speedup vs baseline: 3.4345x; 1.0817x over previous
#include <cuda_runtime.h>
#include <cstdint>

#define NB 64
#define SL 510
#define SLP 532          // padded step stride (prefetch overrun room, >= 529)
#define NT 9
#define HID 768
#define FULLM 0xffffffffu

// Scratch (no dynamic allocation allowed). Zero-initialized at load.
__device__ float g_emiss[NB * SLP * NT];
__device__ float g_partial[NB];

// ---------------------------------------------------------------------------
// Kernel A: emissions[b, s, t] = dot(hidden[b, s+1, :], weight[t, :]) + bias[t]
// Warp-per-row: each lane owns 24 of the 768 K-elements (6 float4, coalesced
// LDG, MLP=6). Weight from smem at lane-consecutive float4 (conflict-free
// LDS). 9 accumulators reduced via bfly shfl. 32640 warps -> full occupancy.
// ---------------------------------------------------------------------------
__global__ __launch_bounds__(256) void emis_kernel(
    const float* __restrict__ hidden,
    const float* __restrict__ weight,
    const float* __restrict__ bias) {
    __shared__ float4 ws4[NT * 192];        // 27,648 B
    __shared__ float bs[NT];

    int tid = threadIdx.x;
    for (int i = tid; i < NT * 192; i += 256)
        ws4[i] = ((const float4*)weight)[i];
    if (tid < NT) bs[tid] = bias[tid];
    __syncthreads();

    int lane = tid & 31;
    int w = (blockIdx.x << 3) + (tid >> 5);   // warp id == row id
    int b = w / SL;
    int s = w - b * SL;

    const float4* hp =
        (const float4*)(hidden + (size_t)(b * 512 + s + 1) * HID) + lane;

    float4 h[6];
#pragma unroll
    for (int u = 0; u < 6; u++) h[u] = hp[u * 32];

    float acc[NT];
#pragma unroll
    for (int t = 0; t < NT; t++) acc[t] = 0.f;

#pragma unroll
    for (int u = 0; u < 6; u++) {
#pragma unroll
        for (int t = 0; t < NT; t++) {
            float4 wv = ws4[t * 192 + u * 32 + lane];
            acc[t] = fmaf(h[u].x, wv.x, fmaf(h[u].y, wv.y,
                     fmaf(h[u].z, wv.z, fmaf(h[u].w, wv.w, acc[t]))));
        }
    }

#pragma unroll
    for (int t = 0; t < NT; t++) {
#pragma unroll
        for (int off = 16; off > 0; off >>= 1)
            acc[t] += __shfl_xor_sync(FULLM, acc[t], off);
    }

    float* o = g_emiss + ((size_t)b * SLP + s) * NT;
#pragma unroll
    for (int t = 0; t < NT; t++)
        if (lane == t) o[t] = acc[t] + bs[t];
}

// ---------------------------------------------------------------------------
// Kernel B: per-batch CRF, 1 warp per block, 2 blocks per batch:
//   role 0: linear-domain forward (denominator, power-2 rescale per 8-group)
//           + numerator score. Depth-16 emission pipeline (LDG 16 ahead,
//           exp computed 8 steps after its load). Branch-free inner body.
//   role 1: Viterbi max-plus forward + history + parallel backtrack.
// ---------------------------------------------------------------------------
__global__ __launch_bounds__(32) void crf_kernel(
    const int* __restrict__ labels,
    const float* __restrict__ start_t,
    const float* __restrict__ end_t,
    const float* __restrict__ trans,
    float* __restrict__ out) {
    __shared__ int s_lbl[528];
    __shared__ float s_trans[NT * NT];
    __shared__ unsigned char hist[512 * 12];   // rows for s-1 in [0,512)

    int blk = blockIdx.x;
    int b = blk >> 1;
    int role = blk & 1;
    int lane = threadIdx.x;
    bool act = lane < NT;
    int lj = act ? lane : 0;

    const float* em_base = g_emiss + (size_t)b * SLP * NT;
    const int* lbl = labels + b * 512;

    // stage labels; force indices 511..527 to -1 (masks steps 510..512)
    for (int i = lane; i < 512; i += 32) s_lbl[i] = lbl[i];
    __syncwarp();
    if (lane < 17) s_lbl[511 + lane] = -1;
    __syncwarp();

    if (role == 0) {
        // ============== ALPHA (linear, power-2 rescaled) + NUMERATOR =======
        for (int i = lane; i < NT * NT; i += 32) s_trans[i] = trans[i];

        float texp[NT];
#pragma unroll
        for (int i = 0; i < NT; i++) texp[i] = __expf(trans[i * NT + lj]);
        __syncwarp();

        float em0 = act ? em_base[lane] : -1e30f;
        float sv = act ? (start_t[lane] + em0) : 0.f;
        float alpha = act ? __expf(sv) : 0.f;
        int acc_e = 0;

        int l1 = s_lbl[1];
        int tag0 = (l1 >= 0) ? l1 : 0;
        float score = __shfl_sync(FULLM, sv, tag0);
        int prev = tag0;

        // depth-16 pipeline
        float em_cur[8], pe_cur[8], em_nxt[8];
#pragma unroll
        for (int u = 0; u < 8; u++)
            em_cur[u] = act ? em_base[(1 + u) * NT + lane] : -1e30f;
#pragma unroll
        for (int u = 0; u < 8; u++) pe_cur[u] = __expf(em_cur[u]);
#pragma unroll
        for (int u = 0; u < 8; u++)
            em_nxt[u] = act ? em_base[(9 + u) * NT + lane] : -1e30f;

        for (int g = 0; g < 64; ++g) {
            int sbase = 1 + (g << 3);
#pragma unroll
            for (int u = 0; u < 8; u++) {
                int s = sbase + u;
                float em_c = em_cur[u];
                float pe_c = pe_cur[u];
                em_cur[u] = em_nxt[u];
                pe_cur[u] = __expf(em_nxt[u]);           // loaded 8 steps ago
                em_nxt[u] = act ? em_base[(s + 16) * NT + lane] : -1e30f;

                int lblc = s_lbl[s + 1];
                int m = lblc >= 0;
                int tg = m ? lblc : 0;

                float b0 = __shfl_sync(FULLM, alpha, 0);
                float b1 = __shfl_sync(FULLM, alpha, 1);
                float b2 = __shfl_sync(FULLM, alpha, 2);
                float b3 = __shfl_sync(FULLM, alpha, 3);
                float b4 = __shfl_sync(FULLM, alpha, 4);
                float b5 = __shfl_sync(FULLM, alpha, 5);
                float b6 = __shfl_sync(FULLM, alpha, 6);
                float b7 = __shfl_sync(FULLM, alpha, 7);
                float b8 = __shfl_sync(FULLM, alpha, 8);

                float d0 = fmaf(b6, texp[6], fmaf(b3, texp[3], b0 * texp[0]));
                float d1 = fmaf(b7, texp[7], fmaf(b4, texp[4], b1 * texp[1]));
                float d2 = fmaf(b8, texp[8], fmaf(b5, texp[5], b2 * texp[2]));
                float an = ((d0 + d1) + d2) * pe_c;
                alpha = m ? an : alpha;

                // numerator chain, branchless
                float em_tg = __shfl_sync(FULLM, em_c, tg);
                float delta = s_trans[prev * NT + tg] + em_tg;
                score += m ? delta : 0.f;
                prev = m ? tg : prev;
            }
            // power-of-2 rescale (exact) — once per 8-group, s = 8g+8
            float ref = __shfl_sync(FULLM, alpha, 4);
            int Eb = (__float_as_int(ref) >> 23) & 0xff;
            int Es = Eb ? Eb : 127;
            alpha *= __int_as_float((254 - Es) << 23);
            acc_e += Es - 127;
        }

        float fa = act ? alpha * __expf(end_t[lane]) : 0.f;
        fa += __shfl_xor_sync(FULLM, fa, 8);
        fa += __shfl_xor_sync(FULLM, fa, 4);
        fa += __shfl_xor_sync(FULLM, fa, 2);
        fa += __shfl_xor_sync(FULLM, fa, 1);
        float den = __logf(fa) + (float)acc_e * 0.69314718056f;

        float endp = act ? end_t[lane] : 0.f;
        float numer = score + __shfl_sync(FULLM, endp, prev);

        if (lane == 0) g_partial[b] = numer - den;
    } else {
        // ================= VITERBI + HISTORY + PARALLEL BACKTRACK ==========
        float tr[NT];
#pragma unroll
        for (int i = 0; i < NT; i++) tr[i] = trans[i * NT + lj];
        float endv = act ? end_t[lane] : -1e30f;

        float vs = act ? (start_t[lane] + em_base[lane]) : -1e30f;

        float em_ring[8];
#pragma unroll
        for (int u = 0; u < 8; u++)
            em_ring[u] = act ? em_base[(1 + u) * NT + lane] : 0.f;

        for (int g = 0; g < 64; ++g) {
            int sbase = 1 + (g << 3);
#pragma unroll
            for (int u = 0; u < 8; u++) {
                int s = sbase + u;
                float em_c = em_ring[u];
                em_ring[u] = act ? em_base[(s + 8) * NT + lane] : 0.f;

                int lblc = s_lbl[s + 1];
                int m = lblc >= 0;

                float x0 = __shfl_sync(FULLM, vs, 0) + tr[0];
                float x1 = __shfl_sync(FULLM, vs, 1) + tr[1];
                float x2 = __shfl_sync(FULLM, vs, 2) + tr[2];
                float x3 = __shfl_sync(FULLM, vs, 3) + tr[3];
                float x4 = __shfl_sync(FULLM, vs, 4) + tr[4];
                float x5 = __shfl_sync(FULLM, vs, 5) + tr[5];
                float x6 = __shfl_sync(FULLM, vs, 6) + tr[6];
                float x7 = __shfl_sync(FULLM, vs, 7) + tr[7];
                float x8 = __shfl_sync(FULLM, vs, 8) + tr[8];

                // value via fmax tree (critical path)
                float mA = fmaxf(fmaxf(fmaxf(x0, x1), fmaxf(x2, x3)),
                                 fmaxf(fmaxf(x4, x5), fmaxf(x6, fmaxf(x7, x8))));
                float vn = mA + em_c;
                vs = (m && act) ? vn : vs;

                // first-index argmax (off critical path)
                int bi = 8;
                if (x7 == mA) bi = 7;
                if (x6 == mA) bi = 6;
                if (x5 == mA) bi = 5;
                if (x4 == mA) bi = 4;
                if (x3 == mA) bi = 3;
                if (x2 == mA) bi = 2;
                if (x1 == mA) bi = 1;
                if (x0 == mA) bi = 0;

                if (act)                       // pad rows (s>509) never read
                    hist[(s - 1) * 12 + lane] = (unsigned char)(m ? bi : lane);
            }
        }

        // final tag: argmax over 9 with first-index tie-break (16-lane bfly)
        float fv = vs + endv;
        int fi = act ? lane : 15;
#pragma unroll
        for (int off = 8; off > 0; off >>= 1) {
            float ov = __shfl_xor_sync(FULLM, fv, off);
            int oi = __shfl_xor_sync(FULLM, fi, off);
            bool take = (ov > fv) || (ov == fv && oi < fi);
            fv = take ? ov : fv;
            fi = take ? oi : fi;
        }
        int last = __shfl_sync(FULLM, fi, 0);
        __syncwarp();

        // ---- parallel backtrack: 16-step segment maps, nibble-packed ----
        int a = lane * 16;
        int bnd = a + 16 < (SL - 1) ? a + 16 : (SL - 1);   // clamp to 509
        unsigned long long F = 0x876543210ull;             // identity map
        for (int s = bnd - 1; s >= a; --s) {
            const unsigned char* hr = hist + s * 12;
            unsigned long long nF = 0;
#pragma unroll
            for (int t = 0; t < NT; t++) {
                int e = (int)((F >> (4 * t)) & 15);
                nF |= ((unsigned long long)hr[e]) << (4 * t);
            }
            F = nF;
        }

        unsigned int flo = (unsigned int)F;
        unsigned int fhi = (unsigned int)(F >> 32);
        int cur = last;          // state at position 509
        int my_entry = (lane == 31) ? last : 0;
        for (int l = 31; l >= 1; --l) {
            unsigned int lo = __shfl_sync(FULLM, flo, l);
            unsigned int hi = __shfl_sync(FULLM, fhi, l);
            unsigned long long Fl = ((unsigned long long)hi << 32) | lo;
            cur = (int)((Fl >> (4 * cur)) & 15);   // state at pos l*16
            if (lane == l - 1) my_entry = cur;
        }

        float* otag = out + 1 + (size_t)b * SL;
        if (lane == 31) {
            otag[SL - 1] = (s_lbl[SL] >= 0) ? (float)last : 0.f;
        }
        int c2 = my_entry;       // state at position bnd
        for (int s = bnd - 1; s >= a; --s) {
            c2 = hist[s * 12 + c2];
            otag[s] = (s_lbl[s + 1] >= 0) ? (float)c2 : 0.f;
        }
    }
}

// ---------------------------------------------------------------------------
// Kernel C: out[0] = -sum_b partial[b]
// ---------------------------------------------------------------------------
__global__ __launch_bounds__(32) void reduce_kernel(float* __restrict__ out) {
    int l = threadIdx.x;
    float v = g_partial[l] + g_partial[l + 32];
#pragma unroll
    for (int o = 16; o > 0; o >>= 1) v += __shfl_xor_sync(FULLM, v, o);
    if (l == 0) out[0] = -v;
}

// ---------------------------------------------------------------------------
extern "C" void kernel_launch(void* const* d_in, const int* in_sizes, int n_in,
                              void* d_out, int out_size) {
    const float* hidden  = (const float*)d_in[0];
    const int*   labels  = (const int*)d_in[1];
    const float* weight  = (const float*)d_in[2];
    const float* bias    = (const float*)d_in[3];
    const float* start_t = (const float*)d_in[4];
    const float* end_t   = (const float*)d_in[5];
    const float* trans   = (const float*)d_in[6];
    float* out = (float*)d_out;

    emis_kernel<<<4080, 256>>>(hidden, weight, bias);
    crf_kernel<<<2 * NB, 32>>>(labels, start_t, end_t, trans, out);
    reduce_kernel<<<1, 32>>>(out);
}